// round 4
// baseline (speedup 1.0000x reference)
#include <cuda_runtime.h>
#include <cstdint>

// ---------------- problem constants ----------------
#define BATCH 8
#define SEQ   1024
#define DIN   1280
#define RNK   64
#define DOUT  1280
#define EMB   (RNK*DIN + DOUT*RNK)   // 163840
#define UPOFF (RNK*DIN)              // 81920

// ---------------- fragment-layout smem (word units) ----------------
// Frag region = 32 lanes x 4 words (16B/lane), padded to 132 words (528B)
// so loader STS.32s land on >=16 distinct banks (<=2-way conflicts) while
// LDS.128 reads stay fully conflict-free (contiguous 512B per region).
#define RSTRIDE 132
#define STAGE_W (32 * RSTRIDE)       // 16 A-regions + 16 B-regions (GEMM1) or 32 (GEMM2 Wu)
#define A_OFF_W 0
#define B_OFF_W (16 * RSTRIDE)
#define NSTAGE  2
#define HREG_W  (NSTAGE * STAGE_W)   // h in A-frag layout: 32 regions (4 mb x 8 ksteps)
#define SMEM_W  (HREG_W + 32 * RSTRIDE)
#define SMEM_BYTES (SMEM_W * 4)      // 67,584 B... (2*16896 + 16896) = 50688 B
// reduction scratch lives in stage area: 4 pairs x 32 lanes x 36 words
#define SCR_LANE_W 36

__device__ __forceinline__ uint32_t f2tf32(float f) {
    uint32_t r; asm("cvt.rna.tf32.f32 %0, %1;" : "=r"(r) : "f"(f)); return r;
}
__device__ __forceinline__ void mma8(float* c, const uint32_t* a, const uint32_t* b) {
    asm volatile(
        "mma.sync.aligned.m16n8k8.row.col.f32.tf32.tf32.f32 "
        "{%0,%1,%2,%3}, {%4,%5,%6,%7}, {%8,%9}, {%0,%1,%2,%3};"
        : "+f"(c[0]), "+f"(c[1]), "+f"(c[2]), "+f"(c[3])
        : "r"(a[0]), "r"(a[1]), "r"(a[2]), "r"(a[3]),
          "r"(b[0]), "r"(b[1]));
}

extern __shared__ uint32_t smu[];

__global__ __launch_bounds__(256, 1)
void ilora_frag_kernel(const float* __restrict__ x,
                       const float* __restrict__ embed,
                       float* __restrict__ out)
{
    const int t    = threadIdx.x;
    const int wid  = t >> 5;
    const int lane = t & 31;
    const int g    = lane >> 2;     // 0..7
    const int tg   = lane & 3;      // 0..3
    const int bb   = blockIdx.x >> 4;
    const int m0   = (blockIdx.x & 15) * 64;

    const float* xb  = x     + (size_t)bb * SEQ * DIN + (size_t)m0 * DIN;
    const float* wdb = embed + (size_t)bb * EMB;          // W_down [64,1280]
    const float* wub = wdb + UPOFF;                       // W_up   [1280,64]
    float*       ob  = out   + (size_t)bb * SEQ * DOUT + (size_t)m0 * DOUT;

    // GEMM1 warp roles: k-split x m-split x n-split = 2x2x2
    const int wk = wid & 1;          // ksteps {2wk, 2wk+1} of each 32-k tile
    const int wm = (wid >> 1) & 1;   // mblocks {2wm, 2wm+1} (32 m-rows)
    const int wn = wid >> 2;         // npairs  {2wn, 2wn+1} (32 n-cols)
    const int pairid = wid >> 1;     // k-split partner group

    // ---------------- GEMM1 loader precompute (2 float4 / thread / tile) ----------------
    const float* gx[2]; const float* gw[2];
    int sA[2], sB[2];
    #pragma unroll
    for (int q = 0; q < 2; q++) {
        int i  = t + 256 * q;        // 0..511
        int r  = i >> 3;             // 0..63 (row of X / n-row of Wd)
        int c4 = (i & 7) * 4;        // 0..28
        gx[q] = xb  + (size_t)r * DIN + c4;
        gw[q] = wdb + (size_t)r * DIN + c4;
        int ks  = c4 >> 3;
        int p   = (c4 >> 2) & 1;     // (c&7)>=4
        int hi8 = ((r & 15) >= 8) ? 1 : 0;
        // A slot = 2*(cc>=4) + (rr>=8) ; B slot = 2*(n8) + (cc>=4)
        sA[q] = A_OFF_W + ((r >> 4) * 4 + ks) * RSTRIDE + (r & 7) * 16 + (p * 2 + hi8);
        sB[q] = B_OFF_W + ((r >> 4) * 4 + ks) * RSTRIDE + (r & 7) * 16 + (hi8 * 2 + p);
    }

    // prologue: prefetch tiles 0..2 into registers
    float4 rbX[3][2], rbW[3][2];
    #pragma unroll
    for (int pf = 0; pf < 3; pf++)
        #pragma unroll
        for (int q = 0; q < 2; q++) {
            rbX[pf][q] = *(const float4*)(gx[q] + pf * 32);
            rbW[pf][q] = *(const float4*)(gw[q] + pf * 32);
        }

    float C[2][4][4];
    #pragma unroll
    for (int a = 0; a < 2; a++)
        #pragma unroll
        for (int b = 0; b < 4; b++)
            #pragma unroll
            for (int qq = 0; qq < 4; qq++) C[a][b][qq] = 0.f;

    // ---------------- GEMM1 main loop: 40 k-tiles of 32 ----------------
    int slot = 0;
    #pragma unroll 1
    for (int kt = 0; kt < 40; kt++) {
        uint32_t* stg = smu + (kt & 1) * STAGE_W;
        #pragma unroll
        for (int q = 0; q < 2; q++) {
            float4 vx = rbX[slot][q], vw = rbW[slot][q];
            stg[sA[q] +  0] = f2tf32(vx.x);
            stg[sA[q] +  4] = f2tf32(vx.y);
            stg[sA[q] +  8] = f2tf32(vx.z);
            stg[sA[q] + 12] = f2tf32(vx.w);
            stg[sB[q] +  0] = f2tf32(vw.x);
            stg[sB[q] +  4] = f2tf32(vw.y);
            stg[sB[q] +  8] = f2tf32(vw.z);
            stg[sB[q] + 12] = f2tf32(vw.w);
        }
        if (kt + 3 < 40) {
            #pragma unroll
            for (int q = 0; q < 2; q++) {
                rbX[slot][q] = *(const float4*)(gx[q] + (kt + 3) * 32);
                rbW[slot][q] = *(const float4*)(gw[q] + (kt + 3) * 32);
            }
        }
        slot = (slot == 2) ? 0 : slot + 1;
        __syncthreads();

        #pragma unroll
        for (int ks2 = 0; ks2 < 2; ks2++) {
            const int ks = wk * 2 + ks2;
            uint4 a[2], b[2];
            #pragma unroll
            for (int mf = 0; mf < 2; mf++)
                a[mf] = *(const uint4*)(stg + A_OFF_W + ((wm * 2 + mf) * 4 + ks) * RSTRIDE + lane * 4);
            #pragma unroll
            for (int nf = 0; nf < 2; nf++)
                b[nf] = *(const uint4*)(stg + B_OFF_W + ((wn * 2 + nf) * 4 + ks) * RSTRIDE + lane * 4);
            #pragma unroll
            for (int mf = 0; mf < 2; mf++)
                #pragma unroll
                for (int nf = 0; nf < 2; nf++) {
                    mma8(C[mf][nf * 2 + 0], (const uint32_t*)&a[mf], (const uint32_t*)&b[nf]);
                    mma8(C[mf][nf * 2 + 1], (const uint32_t*)&a[mf], ((const uint32_t*)&b[nf]) + 2);
                }
        }
    }

    // ---------------- GEMM2 loader precompute + early prefetch ----------------
    const float* gu[4];
    int sU[4];
    #pragma unroll
    for (int q = 0; q < 4; q++) {
        int i  = t + 256 * q;        // 0..1023
        int n  = i >> 4;             // 0..63
        int k4 = (i & 15) * 4;       // 0..60
        gu[q] = wub + (size_t)n * RNK + k4;
        int ks  = k4 >> 3;
        int p   = (k4 >> 2) & 1;
        int hi8 = ((n & 15) >= 8) ? 1 : 0;
        sU[q] = ((n >> 4) * 8 + ks) * RSTRIDE + (n & 7) * 16 + (hi8 * 2 + p);
    }
    float4 rbU[3][4];
    #pragma unroll
    for (int pf = 0; pf < 3; pf++)
        #pragma unroll
        for (int q = 0; q < 4; q++)
            rbU[pf][q] = *(const float4*)(gu[q] + (size_t)pf * 64 * RNK);

    // ---------------- k-split reduction + park h (A-frag layout, tf32) ----------------
    __syncthreads();
    if (wk == 1) {   // partner stores raw fp32 C to scratch
        uint32_t* scr = smu + pairid * (32 * SCR_LANE_W) + lane * SCR_LANE_W;
        #pragma unroll
        for (int mf = 0; mf < 2; mf++)
            #pragma unroll
            for (int nn = 0; nn < 4; nn++)
                *(float4*)(scr + (mf * 4 + nn) * 4) = *(float4*)C[mf][nn];
    }
    __syncthreads();
    if (wk == 0) {   // reduce + round + park
        const uint32_t* scr = smu + pairid * (32 * SCR_LANE_W) + lane * SCR_LANE_W;
        #pragma unroll
        for (int mf = 0; mf < 2; mf++) {
            #pragma unroll
            for (int nn = 0; nn < 4; nn++) {
                float4 pv = *(const float4*)(scr + (mf * 4 + nn) * 4);
                float v0 = C[mf][nn][0] + pv.x;
                float v1 = C[mf][nn][1] + pv.y;
                float v2 = C[mf][nn][2] + pv.z;
                float v3 = C[mf][nn][3] + pv.w;
                int r0 = wm * 32 + mf * 16 + g;
                int c0 = wn * 32 + nn * 8 + 2 * tg;
                // park value (r,c): region=(r>>4)*8+(c>>3), lane=(r&7)*4+(c&3),
                // slot = 2*((c&7)>=4) + ((r&15)>=8)
                #pragma unroll
                for (int e = 0; e < 4; e++) {
                    int r = r0 + (e >> 1) * 8;
                    int c = c0 + (e & 1);
                    float v = (e == 0) ? v0 : (e == 1) ? v1 : (e == 2) ? v2 : v3;
                    int w = HREG_W + ((r >> 4) * 8 + (c >> 3)) * RSTRIDE
                          + ((r & 7) * 4 + (c & 3)) * 4
                          + (((c & 7) >= 4 ? 2 : 0) + ((r & 15) >= 8 ? 1 : 0));
                    smu[w] = f2tf32(v);
                }
            }
        }
    }
    __syncthreads();

    // ---------------- GEMM2: all 8 warps, m-split 2 x n-split 4 ----------------
    const int wn2 = wid & 3;          // npair (16 n-cols)
    const int wm2 = wid >> 2;         // mblocks {2wm2, 2wm2+1}

    uint4 ah[2][8];
    #pragma unroll
    for (int mf = 0; mf < 2; mf++)
        #pragma unroll
        for (int ks = 0; ks < 8; ks++)
            ah[mf][ks] = *(const uint4*)(smu + HREG_W + ((wm2 * 2 + mf) * 8 + ks) * RSTRIDE + lane * 4);

    int slot2 = 0;
    #pragma unroll 1
    for (int j = 0; j < 20; j++) {
        uint32_t* stg = smu + (j & 1) * STAGE_W;
        #pragma unroll
        for (int q = 0; q < 4; q++) {
            float4 v = rbU[slot2][q];
            stg[sU[q] +  0] = f2tf32(v.x);
            stg[sU[q] +  4] = f2tf32(v.y);
            stg[sU[q] +  8] = f2tf32(v.z);
            stg[sU[q] + 12] = f2tf32(v.w);
        }
        if (j + 3 < 20) {
            #pragma unroll
            for (int q = 0; q < 4; q++)
                rbU[slot2][q] = *(const float4*)(gu[q] + (size_t)(j + 3) * 64 * RNK);
        }
        slot2 = (slot2 == 2) ? 0 : slot2 + 1;
        __syncthreads();

        float O[2][2][4];
        #pragma unroll
        for (int a = 0; a < 2; a++)
            #pragma unroll
            for (int b = 0; b < 2; b++)
                #pragma unroll
                for (int qq = 0; qq < 4; qq++) O[a][b][qq] = 0.f;

        #pragma unroll
        for (int ks = 0; ks < 8; ks++) {
            uint4 b = *(const uint4*)(stg + (wn2 * 8 + ks) * RSTRIDE + lane * 4);
            #pragma unroll
            for (int mf = 0; mf < 2; mf++) {
                mma8(O[mf][0], (const uint32_t*)&ah[mf][ks], (const uint32_t*)&b);
                mma8(O[mf][1], (const uint32_t*)&ah[mf][ks], ((const uint32_t*)&b) + 2);
            }
        }

        // epilogue: float2 stores
        #pragma unroll
        for (int mf = 0; mf < 2; mf++) {
            int r = wm2 * 32 + mf * 16 + g;
            #pragma unroll
            for (int h = 0; h < 2; h++) {
                int c = j * 64 + wn2 * 16 + h * 8 + 2 * tg;
                *(float2*)(ob + (size_t)r       * DOUT + c) = make_float2(O[mf][h][0], O[mf][h][1]);
                *(float2*)(ob + (size_t)(r + 8) * DOUT + c) = make_float2(O[mf][h][2], O[mf][h][3]);
            }
        }
    }
}

extern "C" void kernel_launch(void* const* d_in, const int* in_sizes, int n_in,
                              void* d_out, int out_size)
{
    (void)in_sizes; (void)n_in; (void)out_size;
    const float* x     = (const float*)d_in[0];
    const float* embed = (const float*)d_in[1];
    float*       out   = (float*)d_out;

    cudaFuncSetAttribute(ilora_frag_kernel,
                         cudaFuncAttributeMaxDynamicSharedMemorySize, SMEM_BYTES);
    ilora_frag_kernel<<<BATCH * (SEQ / 64), 256, SMEM_BYTES>>>(x, embed, out);
}

// round 8
// speedup vs baseline: 1.2081x; 1.2081x over previous
#include <cuda_runtime.h>
#include <cstdint>

// ---------------- problem constants ----------------
#define BATCH 8
#define SEQ   1024
#define DIN   1280
#define RNK   64
#define DOUT  1280
#define EMB   (RNK*DIN + DOUT*RNK)   // 163840
#define UPOFF (RNK*DIN)              // 81920

// ---------------- fragment-layout smem (word units) ----------------
#define RSTRIDE 132
#define STAGE_W (32 * RSTRIDE)       // 4224 words per stage
#define B_OFF_W (16 * RSTRIDE)       // B region offset inside a GEMM1 stage
#define H_W     0                    // h (A-frag layout) at [0, 4224)
#define STG_BASE (32 * RSTRIDE)      // stages at 4224 + s*4224  (s=0,1)
#define SCR_BASE (3 * 32 * RSTRIDE)  // k-split scratch AFTER stages (no overlay)
#define SCR_LANE_W 36                // 144 B per lane: 16B-aligned float4 slots
#define SCR_GRP_W (32 * SCR_LANE_W)  // 1152 words per (wk,pair) group
#define SMEM_W  (SCR_BASE + 12 * SCR_GRP_W)   // 12672 + 13824 = 26496 words
#define SMEM_BYTES (SMEM_W * 4)               // 105984 B (< 227KB, 1 CTA/SM)

__device__ __forceinline__ uint32_t f2tf32(float f) {
    uint32_t r; asm("cvt.rna.tf32.f32 %0, %1;" : "=r"(r) : "f"(f)); return r;
}
__device__ __forceinline__ void mma8(float* c, const uint32_t* a, const uint32_t* b) {
    asm volatile(
        "mma.sync.aligned.m16n8k8.row.col.f32.tf32.tf32.f32 "
        "{%0,%1,%2,%3}, {%4,%5,%6,%7}, {%8,%9}, {%0,%1,%2,%3};"
        : "+f"(c[0]), "+f"(c[1]), "+f"(c[2]), "+f"(c[3])
        : "r"(a[0]), "r"(a[1]), "r"(a[2]), "r"(a[3]),
          "r"(b[0]), "r"(b[1]));
}

extern __shared__ uint32_t smu[];

__global__ __launch_bounds__(512, 1)
void ilora_frag2_kernel(const float* __restrict__ x,
                        const float* __restrict__ embed,
                        float* __restrict__ out)
{
    const int t    = threadIdx.x;
    const int wid  = t >> 5;
    const int lane = t & 31;
    const int g    = lane >> 2;
    const int tg   = lane & 3;
    const int bb   = blockIdx.x >> 4;
    const int m0   = (blockIdx.x & 15) * 64;

    const float* xb  = x     + (size_t)bb * SEQ * DIN + (size_t)m0 * DIN;
    const float* wdb = embed + (size_t)bb * EMB;          // W_down [64,1280]
    const float* wub = wdb + UPOFF;                       // W_up   [1280,64]
    float*       ob  = out   + (size_t)bb * SEQ * DOUT + (size_t)m0 * DOUT;

    // GEMM1 warp roles: 4 k-split x 2 m x 2 n (16 warps)
    const int wk = wid & 3;          // kstep within each 32-k tile
    const int wm = (wid >> 2) & 1;   // mblocks {2wm, 2wm+1}
    const int wn = wid >> 3;         // 32-col halves

    // ---------------- GEMM1 loader precompute (1 X chunk + 1 Wd chunk / thread) ----------------
    const int r1  = t >> 3;          // 0..63
    const int c4  = (t & 7) * 4;     // 0..28
    const float* gx = xb  + (size_t)r1 * DIN + c4;
    const float* gw = wdb + (size_t)r1 * DIN + c4;
    int sA, sB;
    {
        int ks  = c4 >> 3;
        int p   = (c4 >> 2) & 1;
        int hi8 = ((r1 & 15) >= 8) ? 1 : 0;
        sA = ((r1 >> 4) * 4 + ks) * RSTRIDE + (r1 & 7) * 16 + (p * 2 + hi8);
        sB = B_OFF_W + ((r1 >> 4) * 4 + ks) * RSTRIDE + (r1 & 7) * 16 + (hi8 * 2 + p);
    }

    // prologue: prefetch tiles 0..2
    float4 rbX[3], rbW[3];
    #pragma unroll
    for (int pf = 0; pf < 3; pf++) {
        rbX[pf] = *(const float4*)(gx + pf * 32);
        rbW[pf] = *(const float4*)(gw + pf * 32);
    }

    #define STS_G1(stg, vx, vw) do {                  \
        (stg)[sA +  0] = f2tf32((vx).x);              \
        (stg)[sA +  4] = f2tf32((vx).y);              \
        (stg)[sA +  8] = f2tf32((vx).z);              \
        (stg)[sA + 12] = f2tf32((vx).w);              \
        (stg)[sB +  0] = f2tf32((vw).x);              \
        (stg)[sB +  4] = f2tf32((vw).y);              \
        (stg)[sB +  8] = f2tf32((vw).z);              \
        (stg)[sB + 12] = f2tf32((vw).w);              \
    } while (0)

    // stage 0 <- tile 0; reload slot 0 <- tile 3
    STS_G1(smu + STG_BASE, rbX[0], rbW[0]);
    rbX[0] = *(const float4*)(gx + 3 * 32);
    rbW[0] = *(const float4*)(gw + 3 * 32);
    __syncthreads();

    float C[2][4][4];
    #pragma unroll
    for (int a = 0; a < 2; a++)
        #pragma unroll
        for (int b = 0; b < 4; b++)
            #pragma unroll
            for (int q = 0; q < 4; q++) C[a][b][q] = 0.f;

    // ---------------- GEMM1 main loop ----------------
    #pragma unroll 1
    for (int kt = 0; kt < 40; kt++) {
        // stores for tile kt+1 issued FIRST (drain before the end barrier)
        if (kt < 39) {
            uint32_t* stgW = smu + STG_BASE + ((kt + 1) & 1) * STAGE_W;
            const int slot = (kt + 1) % 3;
            STS_G1(stgW, rbX[slot], rbW[slot]);
            if (kt + 4 < 40) {
                rbX[slot] = *(const float4*)(gx + (kt + 4) * 32);
                rbW[slot] = *(const float4*)(gw + (kt + 4) * 32);
            }
        }

        const uint32_t* stgR = smu + STG_BASE + (kt & 1) * STAGE_W;
        uint4 a0 = *(const uint4*)(stgR + ((wm * 2 + 0) * 4 + wk) * RSTRIDE + lane * 4);
        uint4 a1 = *(const uint4*)(stgR + ((wm * 2 + 1) * 4 + wk) * RSTRIDE + lane * 4);
        uint4 b0 = *(const uint4*)(stgR + B_OFF_W + ((wn * 2 + 0) * 4 + wk) * RSTRIDE + lane * 4);
        uint4 b1 = *(const uint4*)(stgR + B_OFF_W + ((wn * 2 + 1) * 4 + wk) * RSTRIDE + lane * 4);

        mma8(C[0][0], (const uint32_t*)&a0, (const uint32_t*)&b0);
        mma8(C[0][1], (const uint32_t*)&a0, ((const uint32_t*)&b0) + 2);
        mma8(C[0][2], (const uint32_t*)&a0, (const uint32_t*)&b1);
        mma8(C[0][3], (const uint32_t*)&a0, ((const uint32_t*)&b1) + 2);
        mma8(C[1][0], (const uint32_t*)&a1, (const uint32_t*)&b0);
        mma8(C[1][1], (const uint32_t*)&a1, ((const uint32_t*)&b0) + 2);
        mma8(C[1][2], (const uint32_t*)&a1, (const uint32_t*)&b1);
        mma8(C[1][3], (const uint32_t*)&a1, ((const uint32_t*)&b1) + 2);

        __syncthreads();
    }

    // ---------------- GEMM2 loader precompute + EARLY prefetch (hide behind reduction) ----------------
    const float* gu[2];
    int sU[2];
    #pragma unroll
    for (int q = 0; q < 2; q++) {
        int i  = t + 512 * q;            // 0..1023 : 64 rows x 16 chunks
        int n  = i >> 4;
        int k4 = (i & 15) * 4;
        gu[q] = wub + (size_t)n * RNK + k4;
        int ks  = k4 >> 3;
        int p   = (k4 >> 2) & 1;
        int hi8 = ((n & 15) >= 8) ? 1 : 0;
        sU[q] = ((n >> 4) * 8 + ks) * RSTRIDE + (n & 7) * 16 + (hi8 * 2 + p);
    }
    float4 rbU[3][2];
    #pragma unroll
    for (int pf = 0; pf < 3; pf++)
        #pragma unroll
        for (int q = 0; q < 2; q++)
            rbU[pf][q] = *(const float4*)(gu[q] + (size_t)pf * 64 * RNK);

    // ---------------- 4-way k-split reduction + park h (A-frag tf32) ----------------
    const int pairid = wid >> 2;         // (wm, wn) combo 0..3
    if (wk != 0) {
        uint32_t* scr = smu + SCR_BASE + ((wk - 1) * 4 + pairid) * SCR_GRP_W + lane * SCR_LANE_W;
        #pragma unroll
        for (int mf = 0; mf < 2; mf++)
            #pragma unroll
            for (int nn = 0; nn < 4; nn++)
                *(float4*)(scr + (mf * 4 + nn) * 4) = *(float4*)C[mf][nn];
    }
    __syncthreads();
    if (wk == 0) {
        #pragma unroll
        for (int p = 0; p < 3; p++) {
            const uint32_t* scr = smu + SCR_BASE + (p * 4 + pairid) * SCR_GRP_W + lane * SCR_LANE_W;
            #pragma unroll
            for (int mf = 0; mf < 2; mf++)
                #pragma unroll
                for (int nn = 0; nn < 4; nn++) {
                    float4 v = *(const float4*)(scr + (mf * 4 + nn) * 4);
                    C[mf][nn][0] += v.x; C[mf][nn][1] += v.y;
                    C[mf][nn][2] += v.z; C[mf][nn][3] += v.w;
                }
        }
        // park h: (r,c) -> region (r>>4)*8+(c>>3), word lane*4+slot
        #pragma unroll
        for (int mf = 0; mf < 2; mf++) {
            #pragma unroll
            for (int nn = 0; nn < 4; nn++) {
                int r0 = wm * 32 + mf * 16 + g;
                int c0 = wn * 32 + nn * 8 + 2 * tg;
                #pragma unroll
                for (int e = 0; e < 4; e++) {
                    int r = r0 + (e >> 1) * 8;
                    int c = c0 + (e & 1);
                    int w = H_W + ((r >> 4) * 8 + (c >> 3)) * RSTRIDE
                          + ((r & 7) * 4 + (c & 3)) * 4
                          + (((c & 7) >= 4 ? 2 : 0) + ((r & 15) >= 8 ? 1 : 0));
                    smu[w] = f2tf32(C[mf][nn][e]);
                }
            }
        }
    }
    __syncthreads();

    // ---------------- GEMM2: 16 warps = 2 m x 8 n, h A-frags in registers ----------------
    const int wn2 = wid & 7;             // 8-col block
    const int wm2 = (wid >> 3) & 1;      // 32-row half

    uint4 ah[2][8];
    #pragma unroll
    for (int mf = 0; mf < 2; mf++)
        #pragma unroll
        for (int ks = 0; ks < 8; ks++)
            ah[mf][ks] = *(const uint4*)(smu + H_W + ((wm2 * 2 + mf) * 8 + ks) * RSTRIDE + lane * 4);

    #define STS_G2(stg, slot) do {                                   \
        _Pragma("unroll")                                            \
        for (int q = 0; q < 2; q++) {                                \
            float4 v = rbU[slot][q];                                 \
            (stg)[sU[q] +  0] = f2tf32(v.x);                         \
            (stg)[sU[q] +  4] = f2tf32(v.y);                         \
            (stg)[sU[q] +  8] = f2tf32(v.z);                         \
            (stg)[sU[q] + 12] = f2tf32(v.w);                         \
        }                                                            \
    } while (0)

    // prologue: stage 0 <- Wu tile 0; reload slot 0 <- tile 3
    STS_G2(smu + STG_BASE, 0);
    #pragma unroll
    for (int q = 0; q < 2; q++)
        rbU[0][q] = *(const float4*)(gu[q] + (size_t)3 * 64 * RNK);
    __syncthreads();

    #pragma unroll 1
    for (int j = 0; j < 20; j++) {
        if (j < 19) {
            uint32_t* stgW = smu + STG_BASE + ((j + 1) & 1) * STAGE_W;
            const int slot = (j + 1) % 3;
            STS_G2(stgW, slot);
            if (j + 4 < 20) {
                #pragma unroll
                for (int q = 0; q < 2; q++)
                    rbU[slot][q] = *(const float4*)(gu[q] + (size_t)(j + 4) * 64 * RNK);
            }
        }

        const uint32_t* stgR = smu + STG_BASE + (j & 1) * STAGE_W;

        float O[2][4];
        #pragma unroll
        for (int a = 0; a < 2; a++)
            #pragma unroll
            for (int q = 0; q < 4; q++) O[a][q] = 0.f;

        #pragma unroll
        for (int ks = 0; ks < 8; ks++) {
            uint2 b = *(const uint2*)(stgR + ((wn2 >> 1) * 8 + ks) * RSTRIDE
                                      + lane * 4 + (wn2 & 1) * 2);
            mma8(O[0], (const uint32_t*)&ah[0][ks], (const uint32_t*)&b);
            mma8(O[1], (const uint32_t*)&ah[1][ks], (const uint32_t*)&b);
        }

        // epilogue: float2 coalesced stores
        {
            int c = j * 64 + wn2 * 8 + 2 * tg;
            #pragma unroll
            for (int mf = 0; mf < 2; mf++) {
                int r = wm2 * 32 + mf * 16 + g;
                *(float2*)(ob + (size_t)r       * DOUT + c) = make_float2(O[mf][0], O[mf][1]);
                *(float2*)(ob + (size_t)(r + 8) * DOUT + c) = make_float2(O[mf][2], O[mf][3]);
            }
        }

        __syncthreads();
    }
}

extern "C" void kernel_launch(void* const* d_in, const int* in_sizes, int n_in,
                              void* d_out, int out_size)
{
    (void)in_sizes; (void)n_in; (void)out_size;
    const float* x     = (const float*)d_in[0];
    const float* embed = (const float*)d_in[1];
    float*       out   = (float*)d_out;

    cudaFuncSetAttribute(ilora_frag2_kernel,
                         cudaFuncAttributeMaxDynamicSharedMemorySize, SMEM_BYTES);
    ilora_frag2_kernel<<<BATCH * (SEQ / 64), 512, SMEM_BYTES>>>(x, embed, out);
}

// round 11
// speedup vs baseline: 1.3169x; 1.0900x over previous
#include <cuda_runtime.h>
#include <cstdint>

// ---------------- problem constants ----------------
#define BATCH 8
#define SEQ   1024
#define DIN   1280
#define RNK   64
#define DOUT  1280
#define EMB   (RNK*DIN + DOUT*RNK)   // 163840
#define UPOFF (RNK*DIN)              // 81920
#define KSPL  4                      // GEMM1 k-split
#define KCH   (DIN/KSPL)             // 320 per chunk, 10 tiles of 32

// h partials scratch: [ksplit][b][m][rank] fp32 = 8 MB
__device__ float g_hpart[KSPL * BATCH * SEQ * RNK];

// ---------------- fragment-layout constants (word units) ----------------
#define RS 132                       // region stride (528B): 32 lanes x 4 words + pad

__device__ __forceinline__ uint32_t f2tf32(float f) {
    uint32_t r; asm("cvt.rna.tf32.f32 %0, %1;" : "=r"(r) : "f"(f)); return r;
}
__device__ __forceinline__ void mma8(float* c, const uint32_t* a, const uint32_t* b) {
    asm volatile(
        "mma.sync.aligned.m16n8k8.row.col.f32.tf32.tf32.f32 "
        "{%0,%1,%2,%3}, {%4,%5,%6,%7}, {%8,%9}, {%0,%1,%2,%3};"
        : "+f"(c[0]), "+f"(c[1]), "+f"(c[2]), "+f"(c[3])
        : "r"(a[0]), "r"(a[1]), "r"(a[2]), "r"(a[3]),
          "r"(b[0]), "r"(b[1]));
}

extern __shared__ uint32_t smu[];

// ====================================================================
// Kernel 1: h_part[kc] = X[64 x 320] @ Wd[:, 320-chunk]^T  (tf32 MMA)
// grid = 8b x 16mt x 4kc = 512 CTAs, 256 threads (8 warps: 2k x 2m x 2n)
// ====================================================================
#define ST1_W   (32 * RS)            // stage: 16 A-regions + 16 B-regions
#define B1_OFF  (16 * RS)
#define SCR1    (2 * ST1_W)          // reduction scratch after the 2 stages
#define SM1_W   (SCR1 + 4 * 32 * 36) // 8448 + 4608 = 13056 words
#define SM1_BYTES (SM1_W * 4)        // 52224 B

__global__ __launch_bounds__(256)
void ilora_g1_kernel(const float* __restrict__ x,
                     const float* __restrict__ embed)
{
    const int t    = threadIdx.x;
    const int wid  = t >> 5;
    const int lane = t & 31;
    const int g    = lane >> 2;
    const int tg   = lane & 3;

    const int kc = blockIdx.x & 3;
    const int mt = (blockIdx.x >> 2) & 15;
    const int b  = blockIdx.x >> 6;

    const float* xb  = x + (size_t)b * SEQ * DIN + (size_t)(mt * 64) * DIN + kc * KCH;
    const float* wdb = embed + (size_t)b * EMB + kc * KCH;

    const int wk = wid & 1;          // 2 ksteps each (of 4 per 32-k tile)
    const int wm = (wid >> 1) & 1;   // mblocks {2wm, 2wm+1}
    const int wn = wid >> 2;         // n16 blocks {2wn, 2wn+1}

    // loader: 2 X chunks + 2 Wd chunks (float4) per thread per 32-k tile
    const float* gx[2]; const float* gw[2];
    int sA[2], sB[2];
    #pragma unroll
    for (int q = 0; q < 2; q++) {
        int i  = t + 256 * q;        // 0..511
        int r  = i >> 3;             // 0..63
        int c4 = (i & 7) * 4;
        gx[q] = xb  + (size_t)r * DIN + c4;
        gw[q] = wdb + (size_t)r * DIN + c4;
        int ks  = c4 >> 3;
        int p   = (c4 >> 2) & 1;
        int hi8 = ((r & 15) >= 8) ? 1 : 0;
        sA[q] = ((r >> 4) * 4 + ks) * RS + (r & 7) * 16 + (p * 2 + hi8);
        sB[q] = B1_OFF + ((r >> 4) * 4 + ks) * RS + (r & 7) * 16 + (hi8 * 2 + p);
    }

    // ring-2 register prefetch
    float4 rbX[2][2], rbW[2][2];
    #pragma unroll
    for (int s = 0; s < 2; s++)
        #pragma unroll
        for (int q = 0; q < 2; q++) {
            rbX[s][q] = *(const float4*)(gx[q] + s * 32);
            rbW[s][q] = *(const float4*)(gw[q] + s * 32);
        }

    #define STS1(stg, s) do {                                \
        _Pragma("unroll")                                    \
        for (int q = 0; q < 2; q++) {                        \
            float4 vx = rbX[s][q], vw = rbW[s][q];           \
            (stg)[sA[q] +  0] = f2tf32(vx.x);                \
            (stg)[sA[q] +  4] = f2tf32(vx.y);                \
            (stg)[sA[q] +  8] = f2tf32(vx.z);                \
            (stg)[sA[q] + 12] = f2tf32(vx.w);                \
            (stg)[sB[q] +  0] = f2tf32(vw.x);                \
            (stg)[sB[q] +  4] = f2tf32(vw.y);                \
            (stg)[sB[q] +  8] = f2tf32(vw.z);                \
            (stg)[sB[q] + 12] = f2tf32(vw.w);                \
        }                                                    \
    } while (0)

    // stage0 <- tile0 ; slot0 <- tile2
    STS1(smu, 0);
    #pragma unroll
    for (int q = 0; q < 2; q++) {
        rbX[0][q] = *(const float4*)(gx[q] + 2 * 32);
        rbW[0][q] = *(const float4*)(gw[q] + 2 * 32);
    }
    __syncthreads();

    float C[2][4][4];
    #pragma unroll
    for (int a = 0; a < 2; a++)
        #pragma unroll
        for (int n = 0; n < 4; n++)
            #pragma unroll
            for (int q = 0; q < 4; q++) C[a][n][q] = 0.f;

    #pragma unroll 1
    for (int kt = 0; kt < 10; kt++) {
        if (kt < 9) {                           // stores for tile kt+1 first
            uint32_t* stgW = smu + ((kt + 1) & 1) * ST1_W;
            const int slot = (kt + 1) & 1;
            STS1(stgW, slot);
            if (kt + 3 < 10) {
                #pragma unroll
                for (int q = 0; q < 2; q++) {
                    rbX[slot][q] = *(const float4*)(gx[q] + (kt + 3) * 32);
                    rbW[slot][q] = *(const float4*)(gw[q] + (kt + 3) * 32);
                }
            }
        }

        const uint32_t* stgR = smu + (kt & 1) * ST1_W;
        #pragma unroll
        for (int ks2 = 0; ks2 < 2; ks2++) {
            const int ks = wk * 2 + ks2;
            uint4 a0 = *(const uint4*)(stgR + ((wm * 2 + 0) * 4 + ks) * RS + lane * 4);
            uint4 a1 = *(const uint4*)(stgR + ((wm * 2 + 1) * 4 + ks) * RS + lane * 4);
            uint4 b0 = *(const uint4*)(stgR + B1_OFF + ((wn * 2 + 0) * 4 + ks) * RS + lane * 4);
            uint4 b1 = *(const uint4*)(stgR + B1_OFF + ((wn * 2 + 1) * 4 + ks) * RS + lane * 4);
            mma8(C[0][0], (const uint32_t*)&a0, (const uint32_t*)&b0);
            mma8(C[0][1], (const uint32_t*)&a0, ((const uint32_t*)&b0) + 2);
            mma8(C[0][2], (const uint32_t*)&a0, (const uint32_t*)&b1);
            mma8(C[0][3], (const uint32_t*)&a0, ((const uint32_t*)&b1) + 2);
            mma8(C[1][0], (const uint32_t*)&a1, (const uint32_t*)&b0);
            mma8(C[1][1], (const uint32_t*)&a1, ((const uint32_t*)&b0) + 2);
            mma8(C[1][2], (const uint32_t*)&a1, (const uint32_t*)&b1);
            mma8(C[1][3], (const uint32_t*)&a1, ((const uint32_t*)&b1) + 2);
        }
        __syncthreads();
    }

    // 2-way k-reduce within CTA, then write h_part (fp32, no rounding here)
    const int pairid = wid >> 1;             // (wm, wn) group 0..3
    if (wk == 1) {
        uint32_t* scr = smu + SCR1 + pairid * (32 * 36) + lane * 36;
        #pragma unroll
        for (int mf = 0; mf < 2; mf++)
            #pragma unroll
            for (int nn = 0; nn < 4; nn++)
                *(float4*)(scr + (mf * 4 + nn) * 4) = *(float4*)C[mf][nn];
    }
    __syncthreads();
    if (wk == 0) {
        float* hp = g_hpart + ((size_t)(kc * BATCH + b) * SEQ + mt * 64) * RNK;
        const uint32_t* scr = smu + SCR1 + pairid * (32 * 36) + lane * 36;
        #pragma unroll
        for (int mf = 0; mf < 2; mf++) {
            #pragma unroll
            for (int nn = 0; nn < 4; nn++) {
                float4 v = *(const float4*)(scr + (mf * 4 + nn) * 4);
                float v0 = C[mf][nn][0] + v.x, v1 = C[mf][nn][1] + v.y;
                float v2 = C[mf][nn][2] + v.z, v3 = C[mf][nn][3] + v.w;
                int r = wm * 32 + mf * 16 + g;
                int c = wn * 32 + nn * 8 + 2 * tg;
                *(float2*)(hp + (size_t)r       * RNK + c) = make_float2(v0, v1);
                *(float2*)(hp + (size_t)(r + 8) * RNK + c) = make_float2(v2, v3);
            }
        }
    }
}

// ====================================================================
// Kernel 2: out[128 x 128] = (sum_s h_part[s]) @ Wu^T   (tf32 MMA)
// grid = 8b x 8mt x 10nt = 640 CTAs, 256 threads (8 warps: 2m x 4n)
// ====================================================================
#define HF2     0                    // h frags: 8 mb x 8 ks = 64 regions
#define WF2     (64 * RS)            // Wu frags: 8 n16 x 8 ks = 64 regions
#define SM2_W   (128 * RS)           // 16896 words
#define SM2_BYTES (SM2_W * 4)        // 67584 B

__global__ __launch_bounds__(256)
void ilora_g2_kernel(const float* __restrict__ embed,
                     float* __restrict__ out)
{
    const int t    = threadIdx.x;
    const int wid  = t >> 5;
    const int lane = t & 31;
    const int g    = lane >> 2;
    const int tg   = lane & 3;

    const int nt = blockIdx.x % 10;
    const int mt = (blockIdx.x / 10) & 7;
    const int b  = blockIdx.x / 80;

    const float* wub = embed + (size_t)b * EMB + UPOFF + (size_t)(nt * 128) * RNK;
    float*       ob  = out + (size_t)b * SEQ * DOUT + (size_t)(mt * 128) * DOUT + nt * 128;

    // ---- load h (sum 4 partials) into A-frag layout ----
    const float* hp0 = g_hpart + ((size_t)(0 * BATCH + b) * SEQ + mt * 128) * RNK;
    #pragma unroll
    for (int q = 0; q < 8; q++) {
        int i  = t + 256 * q;            // 0..2047 : 128 rows x 16 chunks
        int r  = i >> 4;
        int k4 = (i & 15) * 4;
        const float* p0 = hp0 + (size_t)r * RNK + k4;
        float4 v0 = *(const float4*)(p0);
        float4 v1 = *(const float4*)(p0 + 1 * BATCH * SEQ * RNK);
        float4 v2 = *(const float4*)(p0 + 2 * (size_t)BATCH * SEQ * RNK);
        float4 v3 = *(const float4*)(p0 + 3 * (size_t)BATCH * SEQ * RNK);
        float sx = (v0.x + v1.x) + (v2.x + v3.x);
        float sy = (v0.y + v1.y) + (v2.y + v3.y);
        float sz = (v0.z + v1.z) + (v2.z + v3.z);
        float sw = (v0.w + v1.w) + (v2.w + v3.w);
        int ks  = k4 >> 3;
        int p   = (k4 >> 2) & 1;
        int hi8 = ((r & 15) >= 8) ? 1 : 0;
        int sH  = HF2 + ((r >> 4) * 8 + ks) * RS + (r & 7) * 16 + (p * 2 + hi8);
        smu[sH +  0] = f2tf32(sx);
        smu[sH +  4] = f2tf32(sy);
        smu[sH +  8] = f2tf32(sz);
        smu[sH + 12] = f2tf32(sw);
    }

    // ---- load Wu into B-frag layout ----
    #pragma unroll
    for (int q = 0; q < 8; q++) {
        int i  = t + 256 * q;            // 0..2047 : 128 n-rows x 16 chunks
        int n  = i >> 4;
        int k4 = (i & 15) * 4;
        float4 v = *(const float4*)(wub + (size_t)n * RNK + k4);
        int ks  = k4 >> 3;
        int p   = (k4 >> 2) & 1;
        int hi8 = ((n & 15) >= 8) ? 1 : 0;
        int sW  = WF2 + ((n >> 4) * 8 + ks) * RS + (n & 7) * 16 + (hi8 * 2 + p);
        smu[sW +  0] = f2tf32(v.x);
        smu[sW +  4] = f2tf32(v.y);
        smu[sW +  8] = f2tf32(v.z);
        smu[sW + 12] = f2tf32(v.w);
    }
    __syncthreads();

    // ---- compute: warp = 64 rows x 32 cols ----
    const int wm2 = wid >> 2;            // 0..1 : row half
    const int wn2 = wid & 3;             // 0..3 : 32-col block

    float O[4][4][4];
    #pragma unroll
    for (int a = 0; a < 4; a++)
        #pragma unroll
        for (int n = 0; n < 4; n++)
            #pragma unroll
            for (int q = 0; q < 4; q++) O[a][n][q] = 0.f;

    #pragma unroll
    for (int ks = 0; ks < 8; ks++) {
        uint4 av[4], bv[2];
        #pragma unroll
        for (int mf = 0; mf < 4; mf++)
            av[mf] = *(const uint4*)(smu + HF2 + ((wm2 * 4 + mf) * 8 + ks) * RS + lane * 4);
        #pragma unroll
        for (int nf = 0; nf < 2; nf++)
            bv[nf] = *(const uint4*)(smu + WF2 + ((wn2 * 2 + nf) * 8 + ks) * RS + lane * 4);
        #pragma unroll
        for (int mf = 0; mf < 4; mf++) {
            mma8(O[mf][0], (const uint32_t*)&av[mf], (const uint32_t*)&bv[0]);
            mma8(O[mf][1], (const uint32_t*)&av[mf], ((const uint32_t*)&bv[0]) + 2);
            mma8(O[mf][2], (const uint32_t*)&av[mf], (const uint32_t*)&bv[1]);
            mma8(O[mf][3], (const uint32_t*)&av[mf], ((const uint32_t*)&bv[1]) + 2);
        }
    }

    // ---- epilogue: float2 stores ----
    #pragma unroll
    for (int mf = 0; mf < 4; mf++) {
        int r = wm2 * 64 + mf * 16 + g;
        #pragma unroll
        for (int nn = 0; nn < 4; nn++) {
            int c = wn2 * 32 + nn * 8 + 2 * tg;
            *(float2*)(ob + (size_t)r       * DOUT + c) = make_float2(O[mf][nn][0], O[mf][nn][1]);
            *(float2*)(ob + (size_t)(r + 8) * DOUT + c) = make_float2(O[mf][nn][2], O[mf][nn][3]);
        }
    }
}

extern "C" void kernel_launch(void* const* d_in, const int* in_sizes, int n_in,
                              void* d_out, int out_size)
{
    (void)in_sizes; (void)n_in; (void)out_size;
    const float* x     = (const float*)d_in[0];
    const float* embed = (const float*)d_in[1];
    float*       out   = (float*)d_out;

    static int inited = 0;
    if (!inited) {
        cudaFuncSetAttribute(ilora_g1_kernel,
                             cudaFuncAttributeMaxDynamicSharedMemorySize, SM1_BYTES);
        cudaFuncSetAttribute(ilora_g2_kernel,
                             cudaFuncAttributeMaxDynamicSharedMemorySize, SM2_BYTES);
        inited = 1;
    }

    ilora_g1_kernel<<<BATCH * 16 * KSPL, 256, SM1_BYTES>>>(x, embed);
    ilora_g2_kernel<<<BATCH * 8 * 10, 256, SM2_BYTES>>>(embed, out);
}

// round 12
// speedup vs baseline: 1.5186x; 1.1532x over previous
#include <cuda_runtime.h>
#include <cstdint>

// ---------------- problem constants ----------------
#define BATCH 8
#define SEQ   1024
#define DIN   1280
#define RNK   64
#define DOUT  1280
#define EMB   (RNK*DIN + DOUT*RNK)   // 163840
#define UPOFF (RNK*DIN)              // 81920
#define KSPL  4                      // GEMM1 k-split
#define KCH   (DIN/KSPL)             // 320 per chunk, 10 tiles of 32

// h partials scratch: [ksplit][b][m][rank] fp32 = 8 MB
__device__ float g_hpart[KSPL * BATCH * SEQ * RNK];

// ---------------- fragment-layout constants (word units) ----------------
#define RS 132                       // region stride (528B): 32 lanes x 4 words + pad

__device__ __forceinline__ uint32_t f2tf32(float f) {
    uint32_t r; asm("cvt.rna.tf32.f32 %0, %1;" : "=r"(r) : "f"(f)); return r;
}
__device__ __forceinline__ void mma8(float* c, const uint32_t* a, const uint32_t* b) {
    asm volatile(
        "mma.sync.aligned.m16n8k8.row.col.f32.tf32.tf32.f32 "
        "{%0,%1,%2,%3}, {%4,%5,%6,%7}, {%8,%9}, {%0,%1,%2,%3};"
        : "+f"(c[0]), "+f"(c[1]), "+f"(c[2]), "+f"(c[3])
        : "r"(a[0]), "r"(a[1]), "r"(a[2]), "r"(a[3]),
          "r"(b[0]), "r"(b[1]));
}

extern __shared__ uint32_t smu[];

// ====================================================================
// Kernel 1: h_part[kc] = X[64 x 320] @ Wd[:, 320-chunk]^T  (tf32 MMA)
// grid = 8b x 16mt x 4kc = 512 CTAs, 256 threads (8 warps: 2k x 2m x 2n)
// __launch_bounds__(256,2): regs<=128 -> 2 CTAs/SM (smem 52KB x2 fits)
// ====================================================================
#define ST1_W   (32 * RS)            // stage: 16 A-regions + 16 B-regions
#define B1_OFF  (16 * RS)
#define SCR1    (2 * ST1_W)          // reduction scratch after the 2 stages
#define SM1_W   (SCR1 + 4 * 32 * 36) // 8448 + 4608 = 13056 words
#define SM1_BYTES (SM1_W * 4)        // 52224 B

__global__ __launch_bounds__(256, 2)
void ilora_g1_kernel(const float* __restrict__ x,
                     const float* __restrict__ embed)
{
    const int t    = threadIdx.x;
    const int wid  = t >> 5;
    const int lane = t & 31;
    const int g    = lane >> 2;
    const int tg   = lane & 3;

    const int kc = blockIdx.x & 3;
    const int mt = (blockIdx.x >> 2) & 15;
    const int b  = blockIdx.x >> 6;

    const float* xb  = x + (size_t)b * SEQ * DIN + (size_t)(mt * 64) * DIN + kc * KCH;
    const float* wdb = embed + (size_t)b * EMB + kc * KCH;

    const int wk = wid & 1;          // 2 ksteps each (of 4 per 32-k tile)
    const int wm = (wid >> 1) & 1;   // mblocks {2wm, 2wm+1}
    const int wn = wid >> 2;         // n16 blocks {2wn, 2wn+1}

    // loader: 2 X chunks + 2 Wd chunks (float4) per thread per 32-k tile
    const float* gx[2]; const float* gw[2];
    int sA[2], sB[2];
    #pragma unroll
    for (int q = 0; q < 2; q++) {
        int i  = t + 256 * q;        // 0..511
        int r  = i >> 3;             // 0..63
        int c4 = (i & 7) * 4;
        gx[q] = xb  + (size_t)r * DIN + c4;
        gw[q] = wdb + (size_t)r * DIN + c4;
        int ks  = c4 >> 3;
        int p   = (c4 >> 2) & 1;
        int hi8 = ((r & 15) >= 8) ? 1 : 0;
        sA[q] = ((r >> 4) * 4 + ks) * RS + (r & 7) * 16 + (p * 2 + hi8);
        sB[q] = B1_OFF + ((r >> 4) * 4 + ks) * RS + (r & 7) * 16 + (hi8 * 2 + p);
    }

    // ring-2 register prefetch
    float4 rbX[2][2], rbW[2][2];
    #pragma unroll
    for (int s = 0; s < 2; s++)
        #pragma unroll
        for (int q = 0; q < 2; q++) {
            rbX[s][q] = *(const float4*)(gx[q] + s * 32);
            rbW[s][q] = *(const float4*)(gw[q] + s * 32);
        }

    #define STS1(stg, s) do {                                \
        _Pragma("unroll")                                    \
        for (int q = 0; q < 2; q++) {                        \
            float4 vx = rbX[s][q], vw = rbW[s][q];           \
            (stg)[sA[q] +  0] = f2tf32(vx.x);                \
            (stg)[sA[q] +  4] = f2tf32(vx.y);                \
            (stg)[sA[q] +  8] = f2tf32(vx.z);                \
            (stg)[sA[q] + 12] = f2tf32(vx.w);                \
            (stg)[sB[q] +  0] = f2tf32(vw.x);                \
            (stg)[sB[q] +  4] = f2tf32(vw.y);                \
            (stg)[sB[q] +  8] = f2tf32(vw.z);                \
            (stg)[sB[q] + 12] = f2tf32(vw.w);                \
        }                                                    \
    } while (0)

    // stage0 <- tile0 ; slot0 <- tile2
    STS1(smu, 0);
    #pragma unroll
    for (int q = 0; q < 2; q++) {
        rbX[0][q] = *(const float4*)(gx[q] + 2 * 32);
        rbW[0][q] = *(const float4*)(gw[q] + 2 * 32);
    }
    __syncthreads();

    float C[2][4][4];
    #pragma unroll
    for (int a = 0; a < 2; a++)
        #pragma unroll
        for (int n = 0; n < 4; n++)
            #pragma unroll
            for (int q = 0; q < 4; q++) C[a][n][q] = 0.f;

    #pragma unroll 1
    for (int kt = 0; kt < 10; kt++) {
        if (kt < 9) {                           // stores for tile kt+1 first
            uint32_t* stgW = smu + ((kt + 1) & 1) * ST1_W;
            const int slot = (kt + 1) & 1;
            STS1(stgW, slot);
            if (kt + 3 < 10) {
                #pragma unroll
                for (int q = 0; q < 2; q++) {
                    rbX[slot][q] = *(const float4*)(gx[q] + (kt + 3) * 32);
                    rbW[slot][q] = *(const float4*)(gw[q] + (kt + 3) * 32);
                }
            }
        }

        const uint32_t* stgR = smu + (kt & 1) * ST1_W;
        #pragma unroll
        for (int ks2 = 0; ks2 < 2; ks2++) {
            const int ks = wk * 2 + ks2;
            uint4 a0 = *(const uint4*)(stgR + ((wm * 2 + 0) * 4 + ks) * RS + lane * 4);
            uint4 a1 = *(const uint4*)(stgR + ((wm * 2 + 1) * 4 + ks) * RS + lane * 4);
            uint4 b0 = *(const uint4*)(stgR + B1_OFF + ((wn * 2 + 0) * 4 + ks) * RS + lane * 4);
            uint4 b1 = *(const uint4*)(stgR + B1_OFF + ((wn * 2 + 1) * 4 + ks) * RS + lane * 4);
            mma8(C[0][0], (const uint32_t*)&a0, (const uint32_t*)&b0);
            mma8(C[0][1], (const uint32_t*)&a0, ((const uint32_t*)&b0) + 2);
            mma8(C[0][2], (const uint32_t*)&a0, (const uint32_t*)&b1);
            mma8(C[0][3], (const uint32_t*)&a0, ((const uint32_t*)&b1) + 2);
            mma8(C[1][0], (const uint32_t*)&a1, (const uint32_t*)&b0);
            mma8(C[1][1], (const uint32_t*)&a1, ((const uint32_t*)&b0) + 2);
            mma8(C[1][2], (const uint32_t*)&a1, (const uint32_t*)&b1);
            mma8(C[1][3], (const uint32_t*)&a1, ((const uint32_t*)&b1) + 2);
        }
        __syncthreads();
    }

    // 2-way k-reduce within CTA, then write h_part (fp32, no rounding here)
    const int pairid = wid >> 1;             // (wm, wn) group 0..3
    if (wk == 1) {
        uint32_t* scr = smu + SCR1 + pairid * (32 * 36) + lane * 36;
        #pragma unroll
        for (int mf = 0; mf < 2; mf++)
            #pragma unroll
            for (int nn = 0; nn < 4; nn++)
                *(float4*)(scr + (mf * 4 + nn) * 4) = *(float4*)C[mf][nn];
    }
    __syncthreads();
    if (wk == 0) {
        float* hp = g_hpart + ((size_t)(kc * BATCH + b) * SEQ + mt * 64) * RNK;
        const uint32_t* scr = smu + SCR1 + pairid * (32 * 36) + lane * 36;
        #pragma unroll
        for (int mf = 0; mf < 2; mf++) {
            #pragma unroll
            for (int nn = 0; nn < 4; nn++) {
                float4 v = *(const float4*)(scr + (mf * 4 + nn) * 4);
                float v0 = C[mf][nn][0] + v.x, v1 = C[mf][nn][1] + v.y;
                float v2 = C[mf][nn][2] + v.z, v3 = C[mf][nn][3] + v.w;
                int r = wm * 32 + mf * 16 + g;
                int c = wn * 32 + nn * 8 + 2 * tg;
                *(float2*)(hp + (size_t)r       * RNK + c) = make_float2(v0, v1);
                *(float2*)(hp + (size_t)(r + 8) * RNK + c) = make_float2(v2, v3);
            }
        }
    }
}

// ====================================================================
// Kernel 2: out[64 x 128] = (sum_s h_part[s]) @ Wu^T   (tf32 MMA)
// grid = 8b x 16mt x 10nt = 1280 CTAs, 256 threads (8 warps: 2m x 4n,
// warp tile 32x32). __launch_bounds__(256,2) -> 2 CTAs/SM.
// ====================================================================
#define HF2     0                    // h frags: 4 mb x 8 ks = 32 regions
#define WF2     (32 * RS)            // Wu frags: 8 n16 x 8 ks = 64 regions
#define SM2_W   (96 * RS)            // 12672 words
#define SM2_BYTES (SM2_W * 4)        // 50688 B

__global__ __launch_bounds__(256, 2)
void ilora_g2_kernel(const float* __restrict__ embed,
                     float* __restrict__ out)
{
    const int t    = threadIdx.x;
    const int wid  = t >> 5;
    const int lane = t & 31;
    const int g    = lane >> 2;
    const int tg   = lane & 3;

    const int nt = blockIdx.x % 10;
    const int mt = (blockIdx.x / 10) & 15;
    const int b  = blockIdx.x / 160;

    const float* wub = embed + (size_t)b * EMB + UPOFF + (size_t)(nt * 128) * RNK;
    float*       ob  = out + (size_t)b * SEQ * DOUT + (size_t)(mt * 64) * DOUT + nt * 128;

    // ---- load h (sum 4 partials) into A-frag layout: 64 rows x 64 k ----
    const float* hp0 = g_hpart + ((size_t)b * SEQ + mt * 64) * RNK;
    #pragma unroll
    for (int q = 0; q < 4; q++) {
        int i  = t + 256 * q;            // 0..1023 : 64 rows x 16 chunks
        int r  = i >> 4;
        int k4 = (i & 15) * 4;
        const float* p0 = hp0 + (size_t)r * RNK + k4;
        float4 v0 = *(const float4*)(p0);
        float4 v1 = *(const float4*)(p0 + 1 * (size_t)BATCH * SEQ * RNK);
        float4 v2 = *(const float4*)(p0 + 2 * (size_t)BATCH * SEQ * RNK);
        float4 v3 = *(const float4*)(p0 + 3 * (size_t)BATCH * SEQ * RNK);
        float sx = (v0.x + v1.x) + (v2.x + v3.x);
        float sy = (v0.y + v1.y) + (v2.y + v3.y);
        float sz = (v0.z + v1.z) + (v2.z + v3.z);
        float sw = (v0.w + v1.w) + (v2.w + v3.w);
        int ks  = k4 >> 3;
        int p   = (k4 >> 2) & 1;
        int hi8 = ((r & 15) >= 8) ? 1 : 0;
        int sH  = HF2 + ((r >> 4) * 8 + ks) * RS + (r & 7) * 16 + (p * 2 + hi8);
        smu[sH +  0] = f2tf32(sx);
        smu[sH +  4] = f2tf32(sy);
        smu[sH +  8] = f2tf32(sz);
        smu[sH + 12] = f2tf32(sw);
    }

    // ---- load Wu into B-frag layout: 128 n-rows x 64 k ----
    #pragma unroll
    for (int q = 0; q < 8; q++) {
        int i  = t + 256 * q;            // 0..2047 : 128 n-rows x 16 chunks
        int n  = i >> 4;
        int k4 = (i & 15) * 4;
        float4 v = *(const float4*)(wub + (size_t)n * RNK + k4);
        int ks  = k4 >> 3;
        int p   = (k4 >> 2) & 1;
        int hi8 = ((n & 15) >= 8) ? 1 : 0;
        int sW  = WF2 + ((n >> 4) * 8 + ks) * RS + (n & 7) * 16 + (hi8 * 2 + p);
        smu[sW +  0] = f2tf32(v.x);
        smu[sW +  4] = f2tf32(v.y);
        smu[sW +  8] = f2tf32(v.z);
        smu[sW + 12] = f2tf32(v.w);
    }
    __syncthreads();

    // ---- compute: warp = 32 rows x 32 cols ----
    const int wm2 = wid >> 2;            // 0..1 : 32-row block
    const int wn2 = wid & 3;             // 0..3 : 32-col block

    float O[2][4][4];
    #pragma unroll
    for (int a = 0; a < 2; a++)
        #pragma unroll
        for (int n = 0; n < 4; n++)
            #pragma unroll
            for (int q = 0; q < 4; q++) O[a][n][q] = 0.f;

    #pragma unroll
    for (int ks = 0; ks < 8; ks++) {
        uint4 av[2], bv[2];
        #pragma unroll
        for (int mf = 0; mf < 2; mf++)
            av[mf] = *(const uint4*)(smu + HF2 + ((wm2 * 2 + mf) * 8 + ks) * RS + lane * 4);
        #pragma unroll
        for (int nf = 0; nf < 2; nf++)
            bv[nf] = *(const uint4*)(smu + WF2 + ((wn2 * 2 + nf) * 8 + ks) * RS + lane * 4);
        #pragma unroll
        for (int mf = 0; mf < 2; mf++) {
            mma8(O[mf][0], (const uint32_t*)&av[mf], (const uint32_t*)&bv[0]);
            mma8(O[mf][1], (const uint32_t*)&av[mf], ((const uint32_t*)&bv[0]) + 2);
            mma8(O[mf][2], (const uint32_t*)&av[mf], (const uint32_t*)&bv[1]);
            mma8(O[mf][3], (const uint32_t*)&av[mf], ((const uint32_t*)&bv[1]) + 2);
        }
    }

    // ---- epilogue: float2 stores ----
    #pragma unroll
    for (int mf = 0; mf < 2; mf++) {
        int r = wm2 * 32 + mf * 16 + g;
        #pragma unroll
        for (int nn = 0; nn < 4; nn++) {
            int c = wn2 * 32 + nn * 8 + 2 * tg;
            *(float2*)(ob + (size_t)r       * DOUT + c) = make_float2(O[mf][nn][0], O[mf][nn][1]);
            *(float2*)(ob + (size_t)(r + 8) * DOUT + c) = make_float2(O[mf][nn][2], O[mf][nn][3]);
        }
    }
}

extern "C" void kernel_launch(void* const* d_in, const int* in_sizes, int n_in,
                              void* d_out, int out_size)
{
    (void)in_sizes; (void)n_in; (void)out_size;
    const float* x     = (const float*)d_in[0];
    const float* embed = (const float*)d_in[1];
    float*       out   = (float*)d_out;

    static int inited = 0;
    if (!inited) {
        cudaFuncSetAttribute(ilora_g1_kernel,
                             cudaFuncAttributeMaxDynamicSharedMemorySize, SM1_BYTES);
        cudaFuncSetAttribute(ilora_g2_kernel,
                             cudaFuncAttributeMaxDynamicSharedMemorySize, SM2_BYTES);
        inited = 1;
    }

    ilora_g1_kernel<<<BATCH * 16 * KSPL, 256, SM1_BYTES>>>(x, embed);
    ilora_g2_kernel<<<BATCH * 16 * 10, 256, SM2_BYTES>>>(embed, out);
}